// round 1
// baseline (speedup 1.0000x reference)
#include <cuda_runtime.h>
#include <math.h>
#include <float.h>

#define B_  8
#define L_  1024
#define D_  512
#define NJ  2047     // L+S-1
#define NK  513      // rfft bins of length-1024 signal
#define TOPK 20

// ---------------- scratch (no allocations allowed) ----------------
__device__ float  g_G[B_ * D_ * D_];        // 8 MB Gram matrices
__device__ float  g_cbar[B_ * L_];          // mean circular correlation
__device__ float2 g_spec[B_ * NK];          // rfft of cbar
__device__ float  g_mean[B_ * NJ];          // interpolated mean_value
__device__ float  g_w[B_ * TOPK];           // softmax weights
__device__ int    g_shift[TOPK];            // batch-0 top indices
__device__ float2 g_tw1024[1024];           // e^{-2pi i m/1024}
__device__ float2 g_tw2047[2047];           // e^{+2pi i m/2047}

// ---------------- twiddle init ----------------
__global__ void init_tw_kernel() {
    int i = blockIdx.x * blockDim.x + threadIdx.x;
    const double PI2 = 6.283185307179586476925286766559;
    if (i < 1024) {
        double a = -PI2 * (double)i / 1024.0;
        g_tw1024[i] = make_float2((float)cos(a), (float)sin(a));
    }
    if (i < 2047) {
        double a = PI2 * (double)i / 2047.0;
        g_tw2047[i] = make_float2((float)cos(a), (float)sin(a));
    }
}

// ---------------- GEMM: G[b] = Q[b]^T * K[b]   (512x512, K=1024) ----------------
// grid (4,4,8), block 256, 128x128 tile, BK=8, double buffered.
__global__ __launch_bounds__(256) void gemm_qtk_kernel(const float* __restrict__ Qg,
                                                       const float* __restrict__ Kg) {
    const int b  = blockIdx.z;
    const int t0 = blockIdx.y * 128;
    const int u0 = blockIdx.x * 128;
    const float* A  = Qg + (size_t)b * L_ * D_;
    const float* Bp = Kg + (size_t)b * L_ * D_;
    float* C = g_G + (size_t)b * D_ * D_;

    __shared__ float As[2][8][128];
    __shared__ float Bs[2][8][128];

    const int tid  = threadIdx.x;
    const int lrow = tid >> 5;            // 0..7   (one warp per k-row)
    const int c4   = (tid & 31) << 2;     // 0..124
    const int tx   = tid & 15;            // 0..15
    const int ty   = tid >> 4;            // 0..15

    float acc[8][8];
    #pragma unroll
    for (int i = 0; i < 8; ++i)
        #pragma unroll
        for (int j = 0; j < 8; ++j) acc[i][j] = 0.0f;

    // prologue: k-tile 0
    float4 av = *(const float4*)&A [(size_t)lrow * D_ + t0 + c4];
    float4 bv = *(const float4*)&Bp[(size_t)lrow * D_ + u0 + c4];
    *(float4*)&As[0][lrow][c4] = av;
    *(float4*)&Bs[0][lrow][c4] = bv;
    __syncthreads();

    int buf = 0;
    for (int kt = 0; kt < 128; ++kt) {
        if (kt < 127) {
            int ln = (kt + 1) * 8 + lrow;
            av = *(const float4*)&A [(size_t)ln * D_ + t0 + c4];
            bv = *(const float4*)&Bp[(size_t)ln * D_ + u0 + c4];
        }
        #pragma unroll
        for (int kk = 0; kk < 8; ++kk) {
            float4 a0 = *(const float4*)&As[buf][kk][(ty << 2)];
            float4 a1 = *(const float4*)&As[buf][kk][64 + (ty << 2)];
            float4 b0 = *(const float4*)&Bs[buf][kk][(tx << 2)];
            float4 b1 = *(const float4*)&Bs[buf][kk][64 + (tx << 2)];
            float ar[8] = {a0.x, a0.y, a0.z, a0.w, a1.x, a1.y, a1.z, a1.w};
            float br[8] = {b0.x, b0.y, b0.z, b0.w, b1.x, b1.y, b1.z, b1.w};
            #pragma unroll
            for (int i = 0; i < 8; ++i)
                #pragma unroll
                for (int j = 0; j < 8; ++j)
                    acc[i][j] = fmaf(ar[i], br[j], acc[i][j]);
        }
        if (kt < 127) {
            __syncthreads();
            buf ^= 1;
            *(float4*)&As[buf][lrow][c4] = av;
            *(float4*)&Bs[buf][lrow][c4] = bv;
            __syncthreads();
        }
    }

    #pragma unroll
    for (int i = 0; i < 8; ++i) {
        int r = (i < 4) ? (ty * 4 + i) : (64 + ty * 4 + (i - 4));
        float4 v0 = make_float4(acc[i][0], acc[i][1], acc[i][2], acc[i][3]);
        float4 v1 = make_float4(acc[i][4], acc[i][5], acc[i][6], acc[i][7]);
        *(float4*)&C[(size_t)(t0 + r) * D_ + u0 + (tx << 2)]      = v0;
        *(float4*)&C[(size_t)(t0 + r) * D_ + u0 + 64 + (tx << 2)] = v1;
    }
}

// ---------------- diagonal sums: cbar[b,m] = (1/L) sum_t G[b,t,(t-m) mod 1024] ----------------
// one warp per (b,m); 8192 warps -> 1024 blocks x 256
__global__ __launch_bounds__(256) void diag_kernel() {
    int gw   = (blockIdx.x * blockDim.x + threadIdx.x) >> 5;
    int lane = threadIdx.x & 31;
    int b = gw >> 10;
    int m = gw & 1023;
    if (b >= B_) return;
    const float* Gb = g_G + (size_t)b * D_ * D_;
    float s = 0.0f;
    if (m < 512) {
        for (int t = m + lane; t < 512; t += 32) s += Gb[t * D_ + (t - m)];
    } else if (m > 512) {
        int n = m - 512;                      // t in [0, m-513]
        int off = 1024 - m;
        for (int t = lane; t < n; t += 32) s += Gb[t * D_ + (t + off)];
    }
    #pragma unroll
    for (int o = 16; o > 0; o >>= 1) s += __shfl_xor_sync(0xffffffffu, s, o);
    if (lane == 0) g_cbar[b * L_ + m] = s * (1.0f / (float)L_);
}

// ---------------- spectrum: C_k = sum_m cbar[m] e^{-2pi i km/1024}, k=0..512 ----------------
__global__ __launch_bounds__(256) void spec_kernel() {
    int b = blockIdx.x;
    __shared__ float  sc[1024];
    __shared__ float2 stw[1024];
    for (int i = threadIdx.x; i < 1024; i += 256) { sc[i] = g_cbar[b * L_ + i]; stw[i] = g_tw1024[i]; }
    __syncthreads();
    for (int k = threadIdx.x; k < NK; k += 256) {
        float re = 0.0f, im = 0.0f;
        int idx = 0;
        for (int m = 0; m < 1024; ++m) {
            float2 w = stw[idx];
            float  c = sc[m];
            re = fmaf(c, w.x, re);
            im = fmaf(c, w.y, im);
            idx = (idx + k) & 1023;
        }
        g_spec[b * NK + k] = make_float2(re, im);
    }
}

// ---------------- interpolation: mean[b,j] = (C0 + 2 sum Re(C_k e^{2pi i kj/2047}))/2047 ----------------
__global__ __launch_bounds__(256) void meanval_kernel() {
    int b = blockIdx.y;
    int j = blockIdx.x * 256 + threadIdx.x;
    __shared__ float2 ss[NK];
    __shared__ float2 st[NJ];
    for (int i = threadIdx.x; i < NK; i += 256) ss[i] = g_spec[b * NK + i];
    for (int i = threadIdx.x; i < NJ; i += 256) st[i] = g_tw2047[i];
    __syncthreads();
    if (j >= NJ) return;
    float acc = ss[0].x;
    int idx = 0;
    #pragma unroll 4
    for (int k = 1; k <= 512; ++k) {
        idx += j; if (idx >= NJ) idx -= NJ;
        float2 w = st[idx];
        acc += 2.0f * (ss[k].x * w.x - ss[k].y * w.y);
    }
    g_mean[b * NJ + j] = acc * (1.0f / (float)NJ);
}

// ---------------- top-20 (sorted desc, ties -> lower index) + softmax ----------------
__global__ __launch_bounds__(256) void topk_kernel() {
    int b = blockIdx.x;
    __shared__ float sv[NJ];
    __shared__ float bval[256];
    __shared__ int   bidx[256];
    __shared__ float topv[TOPK];
    __shared__ int   topi[TOPK];
    for (int i = threadIdx.x; i < NJ; i += 256) sv[i] = g_mean[b * NJ + i];
    __syncthreads();
    for (int r = 0; r < TOPK; ++r) {
        float best = -FLT_MAX; int bi = NJ;
        for (int i = threadIdx.x; i < NJ; i += 256) {
            float v = sv[i];
            if (v > best || (v == best && i < bi)) { best = v; bi = i; }
        }
        bval[threadIdx.x] = best; bidx[threadIdx.x] = bi;
        __syncthreads();
        for (int s = 128; s > 0; s >>= 1) {
            if (threadIdx.x < s) {
                float v2 = bval[threadIdx.x + s]; int i2 = bidx[threadIdx.x + s];
                float v1 = bval[threadIdx.x];     int i1 = bidx[threadIdx.x];
                if (v2 > v1 || (v2 == v1 && i2 < i1)) { bval[threadIdx.x] = v2; bidx[threadIdx.x] = i2; }
            }
            __syncthreads();
        }
        if (threadIdx.x == 0) {
            topv[r] = bval[0]; topi[r] = bidx[0];
            sv[bidx[0]] = -FLT_MAX;
        }
        __syncthreads();
    }
    if (threadIdx.x == 0) {
        float mx = topv[0];
        float e[TOPK]; float s = 0.0f;
        for (int k = 0; k < TOPK; ++k) { e[k] = expf(topv[k] - mx); s += e[k]; }
        float inv = 1.0f / s;
        for (int k = 0; k < TOPK; ++k) g_w[b * TOPK + k] = e[k] * inv;
        if (b == 0) for (int k = 0; k < TOPK; ++k) g_shift[k] = topi[k];
    }
}

// ---------------- gather: out[b,l,d] = sum_k w[b,k] * V[b,(l+shift[k])&1023,d] ----------------
// grid (64, 8): blockIdx.x = d-tile of 8 floats, blockIdx.y = b
__global__ __launch_bounds__(256) void gather_kernel(const float* __restrict__ V,
                                                     float* __restrict__ out) {
    int b  = blockIdx.y;
    int d0 = blockIdx.x * 8;
    __shared__ float sv[L_ * 8];
    __shared__ float sw[TOPK];
    __shared__ int   ssh[TOPK];
    const float* Vb = V + (size_t)b * L_ * D_;
    for (int idx = threadIdx.x; idx < L_ * 8; idx += 256) {
        int row = idx >> 3, c = idx & 7;
        sv[idx] = Vb[(size_t)row * D_ + d0 + c];
    }
    if (threadIdx.x < TOPK) {
        sw[threadIdx.x]  = g_w[b * TOPK + threadIdx.x];
        ssh[threadIdx.x] = g_shift[threadIdx.x] & (L_ - 1);
    }
    __syncthreads();
    int d  = threadIdx.x & 7;
    int lb = threadIdx.x >> 3;
    float* ob = out + (size_t)b * L_ * D_ + d0 + d;
    for (int l = lb; l < L_; l += 32) {
        float acc = 0.0f;
        #pragma unroll
        for (int k = 0; k < TOPK; ++k) {
            int row = (l + ssh[k]) & (L_ - 1);
            acc = fmaf(sw[k], sv[(row << 3) + d], acc);
        }
        ob[(size_t)l * D_] = acc;
    }
}

// ---------------- launch ----------------
extern "C" void kernel_launch(void* const* d_in, const int* in_sizes, int n_in,
                              void* d_out, int out_size) {
    const float* q = (const float*)d_in[0];
    const float* k = (const float*)d_in[1];
    const float* v = (const float*)d_in[2];
    float* out = (float*)d_out;

    init_tw_kernel<<<8, 256>>>();
    gemm_qtk_kernel<<<dim3(4, 4, B_), 256>>>(q, k);
    diag_kernel<<<(B_ * 1024 * 32) / 256, 256>>>();
    spec_kernel<<<B_, 256>>>();
    meanval_kernel<<<dim3((NJ + 255) / 256, B_), 256>>>();
    topk_kernel<<<B_, 256>>>();
    gather_kernel<<<dim3(D_ / 8, B_), 256>>>(v, out);
}

// round 2
// speedup vs baseline: 1.3149x; 1.3149x over previous
#include <cuda_runtime.h>
#include <math.h>
#include <float.h>

#define B_  8
#define L_  1024
#define D_  512
#define NJ  2047     // L+S-1
#define NK  513      // rfft bins of length-1024 signal
#define TOPK 20

// ---------------- scratch (no allocations allowed) ----------------
__device__ float  g_cbar[B_ * L_];          // mean circular correlation (atomic-accumulated)
__device__ float2 g_spec[B_ * NK];          // rfft of cbar
__device__ float  g_mean[B_ * NJ];          // interpolated mean_value
__device__ float  g_w[B_ * TOPK];           // softmax weights
__device__ int    g_shift[TOPK];            // batch-0 top indices
__device__ float2 g_tw1024[1024];           // e^{-2pi i m/1024}
__device__ float2 g_tw2047[2047];           // e^{+2pi i m/2047}

// ---------------- init: twiddles + zero cbar ----------------
__global__ void init_kernel() {
    int i = blockIdx.x * blockDim.x + threadIdx.x;
    const double PI2 = 6.283185307179586476925286766559;
    if (i < 1024) {
        double a = -PI2 * (double)i / 1024.0;
        g_tw1024[i] = make_float2((float)cos(a), (float)sin(a));
    }
    if (i < 2047) {
        double a = PI2 * (double)i / 2047.0;
        g_tw2047[i] = make_float2((float)cos(a), (float)sin(a));
    }
    if (i < B_ * L_) g_cbar[i] = 0.0f;
}

// ---------------- GEMM: G[b] = Q[b]^T * K[b] (512x512, K=1024), fused diagonal-sum epilogue ---------
// grid (4,4,8), block 256, 128x128 tile, BK=8, double buffered.
// Instead of storing G, each entry G[t,u] is folded into cbar[b, (t-u)&1023] * (1/1024).
__global__ __launch_bounds__(256) void gemm_qtk_kernel(const float* __restrict__ Qg,
                                                       const float* __restrict__ Kg) {
    const int b  = blockIdx.z;
    const int t0 = blockIdx.y * 128;
    const int u0 = blockIdx.x * 128;
    const float* A  = Qg + (size_t)b * L_ * D_;
    const float* Bp = Kg + (size_t)b * L_ * D_;

    __shared__ float As[2][8][128];
    __shared__ float Bs[2][8][128];
    __shared__ float hist[1024];

    const int tid  = threadIdx.x;
    const int lrow = tid >> 5;            // 0..7   (one warp per k-row)
    const int c4   = (tid & 31) << 2;     // 0..124
    const int tx   = tid & 15;            // 0..15
    const int ty   = tid >> 4;            // 0..15

    for (int i = tid; i < 1024; i += 256) hist[i] = 0.0f;

    float acc[8][8];
    #pragma unroll
    for (int i = 0; i < 8; ++i)
        #pragma unroll
        for (int j = 0; j < 8; ++j) acc[i][j] = 0.0f;

    // prologue: k-tile 0
    float4 av = *(const float4*)&A [(size_t)lrow * D_ + t0 + c4];
    float4 bv = *(const float4*)&Bp[(size_t)lrow * D_ + u0 + c4];
    *(float4*)&As[0][lrow][c4] = av;
    *(float4*)&Bs[0][lrow][c4] = bv;
    __syncthreads();

    int buf = 0;
    for (int kt = 0; kt < 128; ++kt) {
        if (kt < 127) {
            int ln = (kt + 1) * 8 + lrow;
            av = *(const float4*)&A [(size_t)ln * D_ + t0 + c4];
            bv = *(const float4*)&Bp[(size_t)ln * D_ + u0 + c4];
        }
        #pragma unroll
        for (int kk = 0; kk < 8; ++kk) {
            float4 a0 = *(const float4*)&As[buf][kk][(ty << 2)];
            float4 a1 = *(const float4*)&As[buf][kk][64 + (ty << 2)];
            float4 b0 = *(const float4*)&Bs[buf][kk][(tx << 2)];
            float4 b1 = *(const float4*)&Bs[buf][kk][64 + (tx << 2)];
            float ar[8] = {a0.x, a0.y, a0.z, a0.w, a1.x, a1.y, a1.z, a1.w};
            float br[8] = {b0.x, b0.y, b0.z, b0.w, b1.x, b1.y, b1.z, b1.w};
            #pragma unroll
            for (int i = 0; i < 8; ++i)
                #pragma unroll
                for (int j = 0; j < 8; ++j)
                    acc[i][j] = fmaf(ar[i], br[j], acc[i][j]);
        }
        if (kt < 127) {
            __syncthreads();
            buf ^= 1;
            *(float4*)&As[buf][lrow][c4] = av;
            *(float4*)&Bs[buf][lrow][c4] = bv;
            __syncthreads();
        }
    }

    // epilogue: fold acc[8][8] into diagonal histogram.
    // rows: t = t0 + qi*64 + ty*4 + i (i=0..3), cols: u = u0 + qj*64 + tx*4 + j (j=0..3)
    #pragma unroll
    for (int qi = 0; qi < 2; ++qi) {
        #pragma unroll
        for (int qj = 0; qj < 2; ++qj) {
            float dsum[7] = {0, 0, 0, 0, 0, 0, 0};
            #pragma unroll
            for (int i = 0; i < 4; ++i)
                #pragma unroll
                for (int j = 0; j < 4; ++j)
                    dsum[i - j + 3] += acc[qi * 4 + i][qj * 4 + j];
            int base = (t0 + qi * 64 + ty * 4) - (u0 + qj * 64 + tx * 4);
            #pragma unroll
            for (int d = 0; d < 7; ++d)
                atomicAdd(&hist[(base + d - 3) & 1023], dsum[d]);
        }
    }
    __syncthreads();
    for (int i = tid; i < 1024; i += 256) {
        float v = hist[i];
        if (v != 0.0f) atomicAdd(&g_cbar[b * L_ + i], v * (1.0f / (float)L_));
    }
}

// ---------------- spectrum: C_k = sum_m cbar[m] e^{-2pi i km/1024}, k=0..512 ----------------
// one warp per (b,k): 513 blocks x 8 warps
__global__ __launch_bounds__(256) void spec_kernel() {
    int gw   = blockIdx.x * 8 + (threadIdx.x >> 5);
    int lane = threadIdx.x & 31;
    int b = gw & 7;
    int k = gw >> 3;
    const float* cb = g_cbar + b * L_;
    float re = 0.0f, im = 0.0f;
    int idx  = (k * lane) & 1023;
    int step = (k * 32) & 1023;
    int m = lane;
    #pragma unroll 8
    for (int i = 0; i < 32; ++i) {
        float  c = cb[m];
        float2 w = g_tw1024[idx];
        re = fmaf(c, w.x, re);
        im = fmaf(c, w.y, im);
        m += 32;
        idx = (idx + step) & 1023;
    }
    #pragma unroll
    for (int o = 16; o > 0; o >>= 1) {
        re += __shfl_xor_sync(0xffffffffu, re, o);
        im += __shfl_xor_sync(0xffffffffu, im, o);
    }
    if (lane == 0) g_spec[b * NK + k] = make_float2(re, im);
}

// ---------------- interpolation: mean[b,j] = (C0 + 2 sum_{k=1}^{512} Re(C_k e^{2pi i kj/2047}))/2047 ----
// one warp per (b,j): 2047 blocks x 8 warps
__global__ __launch_bounds__(256) void meanval_kernel() {
    int gw   = blockIdx.x * 8 + (threadIdx.x >> 5);
    int lane = threadIdx.x & 31;
    int b = gw & 7;
    int j = gw >> 3;
    const float2* sp = g_spec + b * NK;
    int idx  = ((lane + 1) * j) % NJ;
    int step = (32 * j) % NJ;
    float acc = 0.0f;
    #pragma unroll
    for (int i = 0; i < 16; ++i) {
        int k = 1 + lane + 32 * i;
        float2 s = sp[k];
        float2 w = g_tw2047[idx];
        acc += s.x * w.x - s.y * w.y;
        idx += step; if (idx >= NJ) idx -= NJ;
    }
    acc *= 2.0f;
    #pragma unroll
    for (int o = 16; o > 0; o >>= 1) acc += __shfl_xor_sync(0xffffffffu, acc, o);
    if (lane == 0) g_mean[b * NJ + j] = (acc + sp[0].x) * (1.0f / (float)NJ);
}

// ---------------- top-20 (sorted desc, ties -> lower index) + softmax ----------------
__global__ __launch_bounds__(256) void topk_kernel() {
    int b = blockIdx.x;
    __shared__ float sv[NJ];
    __shared__ float bval[256];
    __shared__ int   bidx[256];
    __shared__ float topv[TOPK];
    __shared__ int   topi[TOPK];
    for (int i = threadIdx.x; i < NJ; i += 256) sv[i] = g_mean[b * NJ + i];
    __syncthreads();
    for (int r = 0; r < TOPK; ++r) {
        float best = -FLT_MAX; int bi = NJ;
        for (int i = threadIdx.x; i < NJ; i += 256) {
            float v = sv[i];
            if (v > best || (v == best && i < bi)) { best = v; bi = i; }
        }
        bval[threadIdx.x] = best; bidx[threadIdx.x] = bi;
        __syncthreads();
        for (int s = 128; s > 0; s >>= 1) {
            if (threadIdx.x < s) {
                float v2 = bval[threadIdx.x + s]; int i2 = bidx[threadIdx.x + s];
                float v1 = bval[threadIdx.x];     int i1 = bidx[threadIdx.x];
                if (v2 > v1 || (v2 == v1 && i2 < i1)) { bval[threadIdx.x] = v2; bidx[threadIdx.x] = i2; }
            }
            __syncthreads();
        }
        if (threadIdx.x == 0) {
            topv[r] = bval[0]; topi[r] = bidx[0];
            sv[bidx[0]] = -FLT_MAX;
        }
        __syncthreads();
    }
    if (threadIdx.x == 0) {
        float mx = topv[0];
        float e[TOPK]; float s = 0.0f;
        for (int k = 0; k < TOPK; ++k) { e[k] = expf(topv[k] - mx); s += e[k]; }
        float inv = 1.0f / s;
        for (int k = 0; k < TOPK; ++k) g_w[b * TOPK + k] = e[k] * inv;
        if (b == 0) for (int k = 0; k < TOPK; ++k) g_shift[k] = topi[k];
    }
}

// ---------------- gather: out[b,l,d] = sum_k w[b,k] * V[b,(l+shift[k])&1023,d] ----------------
// grid (64, 8): blockIdx.x = d-tile of 8 floats, blockIdx.y = b
__global__ __launch_bounds__(256) void gather_kernel(const float* __restrict__ V,
                                                     float* __restrict__ out) {
    int b  = blockIdx.y;
    int d0 = blockIdx.x * 8;
    __shared__ float sv[L_ * 8];
    __shared__ float sw[TOPK];
    __shared__ int   ssh[TOPK];
    const float* Vb = V + (size_t)b * L_ * D_;
    for (int idx = threadIdx.x; idx < L_ * 8; idx += 256) {
        int row = idx >> 3, c = idx & 7;
        sv[idx] = Vb[(size_t)row * D_ + d0 + c];
    }
    if (threadIdx.x < TOPK) {
        sw[threadIdx.x]  = g_w[b * TOPK + threadIdx.x];
        ssh[threadIdx.x] = g_shift[threadIdx.x] & (L_ - 1);
    }
    __syncthreads();
    int d  = threadIdx.x & 7;
    int lb = threadIdx.x >> 3;
    float* ob = out + (size_t)b * L_ * D_ + d0 + d;
    for (int l = lb; l < L_; l += 32) {
        float acc = 0.0f;
        #pragma unroll
        for (int k = 0; k < TOPK; ++k) {
            int row = (l + ssh[k]) & (L_ - 1);
            acc = fmaf(sw[k], sv[(row << 3) + d], acc);
        }
        ob[(size_t)l * D_] = acc;
    }
}

// ---------------- launch ----------------
extern "C" void kernel_launch(void* const* d_in, const int* in_sizes, int n_in,
                              void* d_out, int out_size) {
    const float* q = (const float*)d_in[0];
    const float* k = (const float*)d_in[1];
    const float* v = (const float*)d_in[2];
    float* out = (float*)d_out;

    init_kernel<<<32, 256>>>();
    gemm_qtk_kernel<<<dim3(4, 4, B_), 256>>>(q, k);
    spec_kernel<<<513, 256>>>();
    meanval_kernel<<<NJ, 256>>>();
    topk_kernel<<<B_, 256>>>();
    gather_kernel<<<dim3(D_ / 8, B_), 256>>>(v, out);
}

// round 4
// speedup vs baseline: 2.0127x; 1.5307x over previous
#include <cuda_runtime.h>
#include <cuda_bf16.h>
#include <cstdint>
#include <math.h>
#include <float.h>

#define B_  8
#define L_  1024
#define D_  512
#define NJ  2047
#define NK  513
#define TOPK 20

#define PADB  24             // bf16 per smem tile row (16 data + 8 pad)
#define TILE_B (128*PADB*2)  // bytes per tile = 6144
#define CS 130               // C staging stride (floats)
#define GEMM_SMEM 66560      // max(2*4*6144=49152, 128*130*4=66560)

// ---------------- scratch ----------------
__device__ float  g_cbar[B_ * L_];
__device__ float2 g_spec[B_ * NK];
__device__ float  g_mean[B_ * NJ];
__device__ float  g_w[B_ * TOPK];
__device__ int    g_shift[TOPK];
__device__ __nv_bfloat16 g_Qt_hi[B_ * D_ * L_];
__device__ __nv_bfloat16 g_Qt_lo[B_ * D_ * L_];
__device__ __nv_bfloat16 g_Kt_hi[B_ * D_ * L_];
__device__ __nv_bfloat16 g_Kt_lo[B_ * D_ * L_];

// ---------------- init: zero cbar ----------------
__global__ void init_kernel() {
    int i = blockIdx.x * blockDim.x + threadIdx.x;
    if (i < B_ * L_) g_cbar[i] = 0.0f;
}

// ---------------- convert+transpose: f32 [b][l][d] -> bf16 hi/lo [b][d][l] ----------------
__global__ __launch_bounds__(256) void convert_kernel(const float* __restrict__ Q,
                                                      const float* __restrict__ K) {
    __shared__ float tile[32][33];
    int which = blockIdx.z >> 3;
    int b     = blockIdx.z & 7;
    const float* src = (which ? K : Q) + (size_t)b * L_ * D_;
    __nv_bfloat16* hi = (which ? g_Kt_hi : g_Qt_hi) + (size_t)b * D_ * L_;
    __nv_bfloat16* lo = (which ? g_Kt_lo : g_Qt_lo) + (size_t)b * D_ * L_;
    int l0 = blockIdx.x * 32, d0 = blockIdx.y * 32;
    #pragma unroll
    for (int i = 0; i < 4; ++i)
        tile[threadIdx.y + 8 * i][threadIdx.x] =
            src[(size_t)(l0 + threadIdx.y + 8 * i) * D_ + d0 + threadIdx.x];
    __syncthreads();
    #pragma unroll
    for (int i = 0; i < 4; ++i) {
        float v = tile[threadIdx.x][threadIdx.y + 8 * i];
        int d = d0 + threadIdx.y + 8 * i;
        int l = l0 + threadIdx.x;
        __nv_bfloat16 h = __float2bfloat16(v);
        hi[(size_t)d * L_ + l] = h;
        lo[(size_t)d * L_ + l] = __float2bfloat16(v - __bfloat162float(h));
    }
}

// ---------------- tensor-core GEMM + fused diagonal epilogue ----------------
#define LDSM4(R0, R1, R2, R3, A) \
    asm volatile("ldmatrix.sync.aligned.m8n8.x4.shared.b16 {%0,%1,%2,%3}, [%4];" \
                 : "=r"(R0), "=r"(R1), "=r"(R2), "=r"(R3) : "r"(A))

#define MMA16816(D, A0, A1, A2, A3, B0, B1) \
    asm volatile("mma.sync.aligned.m16n8k16.row.col.f32.bf16.bf16.f32 " \
                 "{%0,%1,%2,%3},{%4,%5,%6,%7},{%8,%9},{%0,%1,%2,%3};" \
                 : "+f"(D[0]), "+f"(D[1]), "+f"(D[2]), "+f"(D[3]) \
                 : "r"(A0), "r"(A1), "r"(A2), "r"(A3), "r"(B0), "r"(B1))

__global__ __launch_bounds__(256, 1) void gemm_kernel() {
    extern __shared__ char sm[];
    const uint32_t smem_base = (uint32_t)__cvta_generic_to_shared(sm);

    const int b  = blockIdx.z;
    const int t0 = blockIdx.y * 128;
    const int u0 = blockIdx.x * 128;
    const __nv_bfloat16* Ahi = g_Qt_hi + (size_t)b * D_ * L_;
    const __nv_bfloat16* Alo = g_Qt_lo + (size_t)b * D_ * L_;
    const __nv_bfloat16* Bhi = g_Kt_hi + (size_t)b * D_ * L_;
    const __nv_bfloat16* Blo = g_Kt_lo + (size_t)b * D_ * L_;

    const int tid  = threadIdx.x;
    const int lane = tid & 31;
    const int warp = tid >> 5;
    const int wm   = warp & 1;      // 2 warps along m
    const int wn   = warp >> 1;     // 4 warps along n

    // gmem staging: thread -> (row, half)
    const int lr = tid >> 1;
    const int lh = tid & 1;
    const size_t a_go = (size_t)(t0 + lr) * L_ + lh * 8;
    const size_t b_go = (size_t)(u0 + lr) * L_ + lh * 8;
    const int s_byte = (lr * PADB + lh * 8) * 2;

    // ldmatrix lane addressing
    const int a_row = lane & 15;
    const int a_col = ((lane >> 4) & 1) * 8;
    const int b_row = ((lane >> 4) << 3) + (lane & 7);
    const int b_col = ((lane >> 3) & 1) * 8;

    float acc[4][4][4];
    #pragma unroll
    for (int i = 0; i < 4; ++i)
        #pragma unroll
        for (int j = 0; j < 4; ++j)
            #pragma unroll
            for (int k = 0; k < 4; ++k) acc[i][j][k] = 0.0f;

    // prologue: k-tile 0 into buffer 0
    {
        char* dst = sm + s_byte;
        *(uint4*)(dst + 0 * TILE_B) = *(const uint4*)&Ahi[a_go];
        *(uint4*)(dst + 1 * TILE_B) = *(const uint4*)&Alo[a_go];
        *(uint4*)(dst + 2 * TILE_B) = *(const uint4*)&Bhi[b_go];
        *(uint4*)(dst + 3 * TILE_B) = *(const uint4*)&Blo[b_go];
    }
    __syncthreads();

    int buf = 0;
    uint4 va_h, va_l, vb_h, vb_l;
    for (int kt = 0; kt < 64; ++kt) {
        if (kt < 63) {
            size_t off = (size_t)(kt + 1) * 16;
            va_h = *(const uint4*)&Ahi[a_go + off];
            va_l = *(const uint4*)&Alo[a_go + off];
            vb_h = *(const uint4*)&Bhi[b_go + off];
            vb_l = *(const uint4*)&Blo[b_go + off];
        }

        const uint32_t base = smem_base + buf * 4 * TILE_B;
        uint32_t ah[4][4], al[4][4], bh[2][4], bl[2][4];
        #pragma unroll
        for (int mt = 0; mt < 4; ++mt) {
            uint32_t addr = base + ((wm * 64 + mt * 16 + a_row) * PADB + a_col) * 2;
            LDSM4(ah[mt][0], ah[mt][1], ah[mt][2], ah[mt][3], addr);
            LDSM4(al[mt][0], al[mt][1], al[mt][2], al[mt][3], addr + TILE_B);
        }
        #pragma unroll
        for (int ng = 0; ng < 2; ++ng) {
            uint32_t addr = base + 2 * TILE_B + ((wn * 32 + ng * 16 + b_row) * PADB + b_col) * 2;
            LDSM4(bh[ng][0], bh[ng][1], bh[ng][2], bh[ng][3], addr);
            LDSM4(bl[ng][0], bl[ng][1], bl[ng][2], bl[ng][3], addr + TILE_B);
        }
        #pragma unroll
        for (int mt = 0; mt < 4; ++mt)
            #pragma unroll
            for (int nt = 0; nt < 4; ++nt) {
                int g = nt >> 1, h = (nt & 1) * 2;
                MMA16816(acc[mt][nt], ah[mt][0], ah[mt][1], ah[mt][2], ah[mt][3],
                         bh[g][h], bh[g][h + 1]);
                MMA16816(acc[mt][nt], al[mt][0], al[mt][1], al[mt][2], al[mt][3],
                         bh[g][h], bh[g][h + 1]);
                MMA16816(acc[mt][nt], ah[mt][0], ah[mt][1], ah[mt][2], ah[mt][3],
                         bl[g][h], bl[g][h + 1]);
            }

        if (kt < 63) {
            char* dst = sm + (buf ^ 1) * 4 * TILE_B + s_byte;
            *(uint4*)(dst + 0 * TILE_B) = va_h;
            *(uint4*)(dst + 1 * TILE_B) = va_l;
            *(uint4*)(dst + 2 * TILE_B) = vb_h;
            *(uint4*)(dst + 3 * TILE_B) = vb_l;
            __syncthreads();
            buf ^= 1;
        }
    }

    // epilogue: stage C in smem, reduce diagonals
    __syncthreads();
    float* Cs = (float*)sm;
    const int cg = lane >> 2, ct = (lane & 3) * 2;
    #pragma unroll
    for (int mt = 0; mt < 4; ++mt)
        #pragma unroll
        for (int nt = 0; nt < 4; ++nt) {
            int m = wm * 64 + mt * 16 + cg;
            int n = wn * 32 + nt * 8 + ct;
            Cs[m * CS + n]           = acc[mt][nt][0];
            Cs[m * CS + n + 1]       = acc[mt][nt][1];
            Cs[(m + 8) * CS + n]     = acc[mt][nt][2];
            Cs[(m + 8) * CS + n + 1] = acc[mt][nt][3];
        }
    __syncthreads();
    if (tid < 255) {
        int dlt = tid - 127;
        int rlo = dlt > 0 ? dlt : 0;
        int rhi = dlt < 0 ? 127 + dlt : 127;
        float s = 0.0f;
        for (int r = rlo; r <= rhi; ++r) s += Cs[r * CS + (r - dlt)];
        int mi = (t0 - u0 + dlt) & 1023;
        atomicAdd(&g_cbar[b * L_ + mi], s * (1.0f / (float)L_));
    }
}

// ---------------- spectrum: one warp per (b,k) ----------------
__global__ __launch_bounds__(256) void spec_kernel() {
    int gw   = blockIdx.x * 8 + (threadIdx.x >> 5);
    int lane = threadIdx.x & 31;
    int b = gw & 7;
    int k = gw >> 3;
    const float* cb = g_cbar + b * L_;
    const float W = -6.283185307179586f / 1024.0f;
    float re = 0.0f, im = 0.0f;
    int idx  = (k * lane) & 1023;
    int step = (k * 32) & 1023;
    int m = lane;
    #pragma unroll 8
    for (int i = 0; i < 32; ++i) {
        float c = cb[m];
        float sn, cs;
        __sincosf(W * (float)idx, &sn, &cs);
        re = fmaf(c, cs, re);
        im = fmaf(c, sn, im);
        m += 32;
        idx = (idx + step) & 1023;
    }
    #pragma unroll
    for (int o = 16; o > 0; o >>= 1) {
        re += __shfl_xor_sync(0xffffffffu, re, o);
        im += __shfl_xor_sync(0xffffffffu, im, o);
    }
    if (lane == 0) g_spec[b * NK + k] = make_float2(re, im);
}

// ---------------- interpolation: one warp per (b,j) ----------------
__global__ __launch_bounds__(256) void meanval_kernel() {
    int gw   = blockIdx.x * 8 + (threadIdx.x >> 5);
    int lane = threadIdx.x & 31;
    int b = gw & 7;
    int j = gw >> 3;
    const float2* sp = g_spec + b * NK;
    const float W = 6.283185307179586f / 2047.0f;
    int idx  = ((lane + 1) * j) % NJ;
    int step = (32 * j) % NJ;
    float acc = 0.0f;
    #pragma unroll
    for (int i = 0; i < 16; ++i) {
        int k = 1 + lane + 32 * i;
        float2 s = sp[k];
        float sn, cs;
        __sincosf(W * (float)idx, &sn, &cs);
        acc += s.x * cs - s.y * sn;
        idx += step; if (idx >= NJ) idx -= NJ;
    }
    acc *= 2.0f;
    #pragma unroll
    for (int o = 16; o > 0; o >>= 1) acc += __shfl_xor_sync(0xffffffffu, acc, o);
    if (lane == 0) g_mean[b * NJ + j] = (acc + sp[0].x) * (1.0f / (float)NJ);
}

// ---------------- top-20 + softmax ----------------
__global__ __launch_bounds__(256) void topk_kernel() {
    int b = blockIdx.x;
    __shared__ float sv[NJ];
    __shared__ float bval[256];
    __shared__ int   bidx[256];
    __shared__ float topv[TOPK];
    __shared__ int   topi[TOPK];
    for (int i = threadIdx.x; i < NJ; i += 256) sv[i] = g_mean[b * NJ + i];
    __syncthreads();
    for (int r = 0; r < TOPK; ++r) {
        float best = -FLT_MAX; int bi = NJ;
        for (int i = threadIdx.x; i < NJ; i += 256) {
            float v = sv[i];
            if (v > best || (v == best && i < bi)) { best = v; bi = i; }
        }
        bval[threadIdx.x] = best; bidx[threadIdx.x] = bi;
        __syncthreads();
        for (int s = 128; s > 0; s >>= 1) {
            if (threadIdx.x < s) {
                float v2 = bval[threadIdx.x + s]; int i2 = bidx[threadIdx.x + s];
                float v1 = bval[threadIdx.x];     int i1 = bidx[threadIdx.x];
                if (v2 > v1 || (v2 == v1 && i2 < i1)) { bval[threadIdx.x] = v2; bidx[threadIdx.x] = i2; }
            }
            __syncthreads();
        }
        if (threadIdx.x == 0) {
            topv[r] = bval[0]; topi[r] = bidx[0];
            sv[bidx[0]] = -FLT_MAX;
        }
        __syncthreads();
    }
    if (threadIdx.x == 0) {
        float mx = topv[0];
        float e[TOPK]; float s = 0.0f;
        for (int k = 0; k < TOPK; ++k) { e[k] = expf(topv[k] - mx); s += e[k]; }
        float inv = 1.0f / s;
        for (int k = 0; k < TOPK; ++k) g_w[b * TOPK + k] = e[k] * inv;
        if (b == 0) for (int k = 0; k < TOPK; ++k) g_shift[k] = topi[k];
    }
}

// ---------------- gather ----------------
__global__ __launch_bounds__(256) void gather_kernel(const float* __restrict__ V,
                                                     float* __restrict__ out) {
    int b  = blockIdx.y;
    int d0 = blockIdx.x * 8;
    __shared__ float sv[L_ * 8];
    __shared__ float sw[TOPK];
    __shared__ int   ssh[TOPK];
    const float* Vb = V + (size_t)b * L_ * D_;
    for (int idx = threadIdx.x; idx < L_ * 8; idx += 256) {
        int row = idx >> 3, c = idx & 7;
        sv[idx] = Vb[(size_t)row * D_ + d0 + c];
    }
    if (threadIdx.x < TOPK) {
        sw[threadIdx.x]  = g_w[b * TOPK + threadIdx.x];
        ssh[threadIdx.x] = g_shift[threadIdx.x] & (L_ - 1);
    }
    __syncthreads();
    int d  = threadIdx.x & 7;
    int lb = threadIdx.x >> 3;
    float* ob = out + (size_t)b * L_ * D_ + d0 + d;
    for (int l = lb; l < L_; l += 32) {
        float acc = 0.0f;
        #pragma unroll
        for (int k = 0; k < TOPK; ++k) {
            int row = (l + ssh[k]) & (L_ - 1);
            acc = fmaf(sw[k], sv[(row << 3) + d], acc);
        }
        ob[(size_t)l * D_] = acc;
    }
}

// ---------------- launch ----------------
extern "C" void kernel_launch(void* const* d_in, const int* in_sizes, int n_in,
                              void* d_out, int out_size) {
    const float* q = (const float*)d_in[0];
    const float* k = (const float*)d_in[1];
    const float* v = (const float*)d_in[2];
    float* out = (float*)d_out;

    cudaFuncSetAttribute(gemm_kernel, cudaFuncAttributeMaxDynamicSharedMemorySize, GEMM_SMEM);

    init_kernel<<<32, 256>>>();
    convert_kernel<<<dim3(32, 16, 16), dim3(32, 8)>>>(q, k);
    gemm_kernel<<<dim3(4, 4, B_), 256, GEMM_SMEM>>>();
    spec_kernel<<<513, 256>>>();
    meanval_kernel<<<NJ, 256>>>();
    topk_kernel<<<B_, 256>>>();
    gather_kernel<<<dim3(D_ / 8, B_), 256>>>(v, out);
}